// round 1
// baseline (speedup 1.0000x reference)
#include <cuda_runtime.h>
#include <math.h>

// Problem constants
#define T_STEPS 16384
#define HID     1024
#define INP     256
#define NLAB    32

#define NCTA    128          // persistent CTAs (<=148 SMs -> single wave, co-resident)
#define TPB     256          // threads per CTA; TPB == INP (each thread owns 1 input col)
#define ROWS    8            // HID / NCTA hidden rows per CTA

// Persistent scratch (allowed: __device__ globals; reset kernel restores state
// every launch so graph replays are deterministic).
__device__ float        g_h[2][HID];     // double-buffered hidden state
__device__ unsigned int g_flags[NCTA];   // g_flags[c] == s  <=>  CTA c has published h_s

__global__ void rnn_reset_kernel() {
    int t = threadIdx.x;
    for (int i = t; i < 2 * HID; i += blockDim.x) ((float*)g_h)[i] = 0.0f;
    if (t < NCTA) g_flags[t] = 0u;
}

__global__ void __launch_bounds__(TPB, 1) rnn_scan_kernel(
    const float* __restrict__ X,    // [T, 1, 256]
    const float* __restrict__ Wi,   // [1024, 256]
    const float* __restrict__ bi,   // [1024]
    const float* __restrict__ Wh,   // [1024, 1024]
    const float* __restrict__ bh,   // [1024]
    const float* __restrict__ Wo,   // [32, 1024]
    const float* __restrict__ bo,   // [32]
    float* __restrict__ out)        // [32] log-softmax
{
    const int c    = blockIdx.x;
    const int t    = threadIdx.x;
    const int lane = t & 31;
    const int warp = t >> 5;

    volatile unsigned int* flags = g_flags;

    // ---- Load this CTA's weight slice into registers (held for all 16384 steps) ----
    // Thread t owns hidden columns [4t, 4t+4) of Wh and input column t of Wi,
    // for all ROWS rows of this CTA.
    float4 wh[ROWS];
    float  wi[ROWS];
    #pragma unroll
    for (int r = 0; r < ROWS; r++) {
        int row = c * ROWS + r;
        wh[r] = ((const float4*)Wh)[row * (HID / 4) + t];
        wi[r] = Wi[row * INP + t];
    }
    float bias = 0.0f;
    if (t < ROWS) bias = bi[c * ROWS + t] + bh[c * ROWS + t];

    __shared__ float s_part[TPB / 32][ROWS];   // per-warp partial sums

    // x for step 0 (thread t owns input dim t)
    float x = X[t];

    for (int s = 0; s < T_STEPS; s++) {
        // Prefetch next step's input element early (independent of h).
        float x_next = 0.0f;
        if (s + 1 < T_STEPS) x_next = X[(s + 1) * INP + t];

        // Input projection partials — computed before/while waiting on h_s.
        float acc[ROWS];
        #pragma unroll
        for (int r = 0; r < ROWS; r++) acc[r] = wi[r] * x;

        // ---- Wait for h_s from all CTAs (flags monotone; s=0 passes immediately) ----
        if (t < NCTA) {
            while (flags[t] < (unsigned)s) { /* spin on L2 */ }
        }
        __threadfence();   // acquire
        __syncthreads();

        // ---- Recurrent GEMV partials: thread t covers h cols [4t, 4t+4) ----
        const float4 h4 = __ldcg((const float4*)g_h[s & 1] + t);
        #pragma unroll
        for (int r = 0; r < ROWS; r++) {
            acc[r] = fmaf(wh[r].x, h4.x, acc[r]);
            acc[r] = fmaf(wh[r].y, h4.y, acc[r]);
            acc[r] = fmaf(wh[r].z, h4.z, acc[r]);
            acc[r] = fmaf(wh[r].w, h4.w, acc[r]);
        }

        // ---- Reduce 256 threads -> 8 row sums ----
        #pragma unroll
        for (int off = 16; off > 0; off >>= 1) {
            #pragma unroll
            for (int r = 0; r < ROWS; r++)
                acc[r] += __shfl_down_sync(0xffffffffu, acc[r], off);
        }
        if (lane == 0) {
            #pragma unroll
            for (int r = 0; r < ROWS; r++) s_part[warp][r] = acc[r];
        }
        __syncthreads();

        if (t < ROWS) {
            float y = bias;
            #pragma unroll
            for (int w = 0; w < TPB / 32; w++) y += s_part[w][t];
            float hnew = tanhf(y);
            __stcg(&g_h[(s + 1) & 1][c * ROWS + t], hnew);
            __threadfence();   // release (data before flag)
        }
        __syncthreads();
        if (t == 0) {
            __threadfence();
            flags[c] = (unsigned)(s + 1);   // publish h_{s+1}
        }

        x = x_next;
    }

    // ---- Epilogue: CTA 0 computes logits + log_softmax on h_T ----
    if (c == 0) {
        if (t < NCTA) {
            while (flags[t] < (unsigned)T_STEPS) { }
        }
        __threadfence();
        __syncthreads();

        const float* hT = g_h[T_STEPS & 1];   // T even -> buffer 0
        int row = t >> 3;       // 32 rows x 8 threads
        int sub = t & 7;
        float acc = 0.0f;
        #pragma unroll 4
        for (int j = 0; j < HID / 8; j += 4) {
            int col = sub * (HID / 8) + j;
            float4 w4 = ((const float4*)Wo)[(row * HID + col) >> 2];
            float4 h4 = __ldcg((const float4*)(hT + col));
            acc = fmaf(w4.x, h4.x, acc);
            acc = fmaf(w4.y, h4.y, acc);
            acc = fmaf(w4.z, h4.z, acc);
            acc = fmaf(w4.w, h4.w, acc);
        }
        // reduce 8 consecutive lanes (same row) within the warp
        acc += __shfl_down_sync(0xffffffffu, acc, 4);
        acc += __shfl_down_sync(0xffffffffu, acc, 2);
        acc += __shfl_down_sync(0xffffffffu, acc, 1);

        __shared__ float s_log[NLAB];
        if (sub == 0) s_log[row] = acc + bo[row];
        __syncthreads();

        if (t < NLAB) {   // warp 0, all 32 lanes
            float v = s_log[t];
            float m = v;
            #pragma unroll
            for (int off = 16; off > 0; off >>= 1)
                m = fmaxf(m, __shfl_xor_sync(0xffffffffu, m, off));
            float e = expf(v - m);
            float ssum = e;
            #pragma unroll
            for (int off = 16; off > 0; off >>= 1)
                ssum += __shfl_xor_sync(0xffffffffu, ssum, off);
            out[t] = v - m - logf(ssum);
        }
    }
}

extern "C" void kernel_launch(void* const* d_in, const int* in_sizes, int n_in,
                              void* d_out, int out_size) {
    const float* X  = (const float*)d_in[0];
    const float* Wi = (const float*)d_in[1];
    const float* bi = (const float*)d_in[2];
    const float* Wh = (const float*)d_in[3];
    const float* bh = (const float*)d_in[4];
    const float* Wo = (const float*)d_in[5];
    const float* bo = (const float*)d_in[6];
    float* out = (float*)d_out;

    rnn_reset_kernel<<<1, 256>>>();
    rnn_scan_kernel<<<NCTA, TPB>>>(X, Wi, bi, Wh, bh, Wo, bo, out);
}